// round 1
// baseline (speedup 1.0000x reference)
#include <cuda_runtime.h>
#include <cuda_bf16.h>
#include <cstdint>

// Problem constants
#define BB   256   // batch
#define TT   512   // time
#define II   300   // input size
#define HH   64    // hidden
#define G3   192   // 3*H

// Scratch: xp[dir][s][b][g]  (dir0 = forward scan order, dir1 = backward scan order)
__device__ float g_xp[2ull * TT * BB * G3];        // 201 MB
__device__ float g_feat[BB * 256];                 // [B, 4H]

// ---------------------------------------------------------------------------
// Kernel 1: input projection GEMM.
// M = B*T = 131072 rows of x (row r = b*512 + t, contiguous 300 floats),
// N = 384 (3 tiles forward W_ih_f, 3 tiles backward W_ih_b), K = 300.
// Block tile 128x64, thread tile 8x4, K chunk 20 (300 = 15*20).
// ---------------------------------------------------------------------------
__global__ void __launch_bounds__(256)
proj_kernel(const float* __restrict__ x,
            const float* __restrict__ Wf, const float* __restrict__ bf,
            const float* __restrict__ Wb, const float* __restrict__ bb)
{
    __shared__ float As[20][132];   // [k][m], padded stride
    __shared__ float Bs[20][68];    // [k][n], padded stride

    const int tid = threadIdx.x;
    const int tx  = tid & 15;       // n direction (4 cols each)
    const int ty  = tid >> 4;       // m direction (8 rows each)
    const int mt  = blockIdx.x;     // 0..1023
    const int nt  = blockIdx.y;     // 0..5

    const float* W;  const float* bias;  int g0, dir;
    if (nt < 3) { W = Wf; bias = bf; g0 = nt * 64;       dir = 0; }
    else        { W = Wb; bias = bb; g0 = (nt - 3) * 64; dir = 1; }

    const int r0 = mt * 128;

    float acc[8][4];
    #pragma unroll
    for (int i = 0; i < 8; i++)
        #pragma unroll
        for (int j = 0; j < 4; j++) acc[i][j] = 0.f;

    for (int k0 = 0; k0 < II; k0 += 20) {
        // Load A tile: 128 rows x 20 k = 640 float4
        for (int i = tid; i < 640; i += 256) {
            const int row = i / 5, q = i % 5;
            float4 v = *(const float4*)(x + (size_t)(r0 + row) * II + k0 + q * 4);
            As[q*4+0][row] = v.x; As[q*4+1][row] = v.y;
            As[q*4+2][row] = v.z; As[q*4+3][row] = v.w;
        }
        // Load B tile: 64 rows x 20 k = 320 float4
        for (int i = tid; i < 320; i += 256) {
            const int row = i / 5, q = i % 5;
            float4 v = *(const float4*)(W + (size_t)(g0 + row) * II + k0 + q * 4);
            Bs[q*4+0][row] = v.x; Bs[q*4+1][row] = v.y;
            Bs[q*4+2][row] = v.z; Bs[q*4+3][row] = v.w;
        }
        __syncthreads();

        #pragma unroll
        for (int k = 0; k < 20; k++) {
            float4 a0 = *(const float4*)&As[k][ty * 8];
            float4 a1 = *(const float4*)&As[k][ty * 8 + 4];
            float4 bv = *(const float4*)&Bs[k][tx * 4];
            float am[8] = {a0.x, a0.y, a0.z, a0.w, a1.x, a1.y, a1.z, a1.w};
            float bn[4] = {bv.x, bv.y, bv.z, bv.w};
            #pragma unroll
            for (int i = 0; i < 8; i++)
                #pragma unroll
                for (int j = 0; j < 4; j++)
                    acc[i][j] += am[i] * bn[j];
        }
        __syncthreads();
    }

    // bias + store to g_xp in scan order
    float bs4[4];
    #pragma unroll
    for (int j = 0; j < 4; j++) bs4[j] = bias[g0 + tx * 4 + j];

    #pragma unroll
    for (int i = 0; i < 8; i++) {
        const int r = r0 + ty * 8 + i;
        const int b = r >> 9;          // /512
        const int t = r & 511;
        const int s = dir ? (TT - 1 - t) : t;
        float4 o;
        o.x = acc[i][0] + bs4[0];
        o.y = acc[i][1] + bs4[1];
        o.z = acc[i][2] + bs4[2];
        o.w = acc[i][3] + bs4[3];
        size_t idx = (((size_t)dir * TT + s) * BB + b) * G3 + g0 + tx * 4;
        *(float4*)&g_xp[idx] = o;
    }
}

// ---------------------------------------------------------------------------
// Kernel 2: GRU recurrence. One block per (dir, batch) chain; 192 threads,
// thread j owns W_hh row j in 64 registers. h[64] broadcast from smem.
// ---------------------------------------------------------------------------
__device__ __forceinline__ float sigmoid_fast(float a) {
    return 1.f / (1.f + __expf(-a));
}
__device__ __forceinline__ float tanh_fast(float a) {
    float c = fminf(fmaxf(a, -20.f), 20.f);
    float e = __expf(2.f * c);
    return (e - 1.f) / (e + 1.f);
}

__global__ void __launch_bounds__(192, 4)
gru_kernel(const float* __restrict__ Whh_f, const float* __restrict__ bhh_f,
           const float* __restrict__ Whh_b, const float* __restrict__ bhh_b)
{
    __shared__ __align__(16) float sh_h[64];
    __shared__ float s_r[64], s_z[64], s_gn[64], s_xn[64];

    const int bid = blockIdx.x;
    const int dir = bid >> 8;      // 0 fwd, 1 bwd
    const int b   = bid & 255;
    const int j   = threadIdx.x;   // 0..191

    const float* W  = dir ? Whh_b : Whh_f;
    const float* bh = dir ? bhh_b : bhh_f;

    float w[64];
    #pragma unroll
    for (int k = 0; k < 64; k += 4) {
        float4 v = *(const float4*)(W + (size_t)j * 64 + k);
        w[k] = v.x; w[k+1] = v.y; w[k+2] = v.z; w[k+3] = v.w;
    }
    const float bias = bh[j];

    if (j < 64) sh_h[j] = 0.f;
    __syncthreads();

    const float* xp_base = g_xp + ((size_t)dir * TT) * BB * G3 + (size_t)b * G3 + j;
    const size_t step_stride = (size_t)BB * G3;

    for (int s = 0; s < TT; s++) {
        const float xp = __ldg(xp_base + (size_t)s * step_stride);

        float a0 = 0.f, a1 = 0.f, a2 = 0.f, a3 = 0.f;
        #pragma unroll
        for (int k = 0; k < 64; k += 4) {
            float4 h4 = *(const float4*)&sh_h[k];
            a0 += w[k]     * h4.x;
            a1 += w[k + 1] * h4.y;
            a2 += w[k + 2] * h4.z;
            a3 += w[k + 3] * h4.w;
        }
        const float gh = bias + ((a0 + a1) + (a2 + a3));
        const float a  = xp + gh;

        if (j < 64)        s_r[j]        = sigmoid_fast(a);
        else if (j < 128)  s_z[j - 64]   = sigmoid_fast(a);
        else             { s_gn[j - 128] = gh; s_xn[j - 128] = xp; }
        __syncthreads();

        if (j < 64) {
            const float r    = s_r[j];
            const float z    = s_z[j];
            const float n    = tanh_fast(s_xn[j] + r * s_gn[j]);
            const float hold = sh_h[j];
            const float hnew = (1.f - z) * n + z * hold;
            sh_h[j] = hnew;
            if (s == 0)
                g_feat[b * 256 + (dir ? 192 : 0) + j] = hnew;   // hs_f[0] / hs_b[0]
        }
        __syncthreads();
    }

    if (j < 64)
        g_feat[b * 256 + (dir ? 64 : 128) + j] = sh_h[j];       // final h
}

// ---------------------------------------------------------------------------
// Kernel 3: head. One warp per batch row: thread j computes h1[j], LeakyReLU,
// warp-reduce the 32-term dot with W2.
// ---------------------------------------------------------------------------
__global__ void __launch_bounds__(32)
head_kernel(const float* __restrict__ W1, const float* __restrict__ b1,
            const float* __restrict__ W2, const float* __restrict__ b2,
            float* __restrict__ out)
{
    const int b = blockIdx.x;
    const int j = threadIdx.x;   // 0..31
    const float* f = g_feat + b * 256;
    const float* w = W1 + (size_t)j * 256;

    float acc = b1[j];
    #pragma unroll 8
    for (int k = 0; k < 256; k += 4) {
        float4 fv = *(const float4*)(f + k);
        float4 wv = *(const float4*)(w + k);
        acc += fv.x * wv.x + fv.y * wv.y + fv.z * wv.z + fv.w * wv.w;
    }
    acc = (acc >= 0.f) ? acc : 0.01f * acc;   // LeakyReLU
    float v = acc * W2[j];
    #pragma unroll
    for (int off = 16; off; off >>= 1)
        v += __shfl_down_sync(0xffffffffu, v, off);
    if (j == 0) out[b] = v + b2[0];
}

// ---------------------------------------------------------------------------
extern "C" void kernel_launch(void* const* d_in, const int* in_sizes, int n_in,
                              void* d_out, int out_size)
{
    const float* x      = (const float*)d_in[0];
    const float* W_ih_f = (const float*)d_in[1];
    const float* W_hh_f = (const float*)d_in[2];
    const float* b_ih_f = (const float*)d_in[3];
    const float* b_hh_f = (const float*)d_in[4];
    const float* W_ih_b = (const float*)d_in[5];
    const float* W_hh_b = (const float*)d_in[6];
    const float* b_ih_b = (const float*)d_in[7];
    const float* b_hh_b = (const float*)d_in[8];
    const float* W1     = (const float*)d_in[9];
    const float* b1     = (const float*)d_in[10];
    const float* W2     = (const float*)d_in[11];
    const float* b2     = (const float*)d_in[12];
    float* out = (float*)d_out;

    proj_kernel<<<dim3(1024, 6), 256>>>(x, W_ih_f, b_ih_f, W_ih_b, b_ih_b);
    gru_kernel<<<512, 192>>>(W_hh_f, b_hh_f, W_hh_b, b_hh_b);
    head_kernel<<<256, 32>>>(W1, b1, W2, b2, out);
}